// round 4
// baseline (speedup 1.0000x reference)
#include <cuda_runtime.h>

#define NMAX   200000
#define HDIM   64
#define CDIM   128
#define KEEPK  63
#define MAXTILES (KEEPK * ((NMAX + 63) / 64))

// ---- device scratch (static; no allocation) ------------------------------
__device__ __align__(16) float g_f  [(size_t)NMAX * HDIM];   // 51.2 MB
__device__ __align__(16) float g_acc[(size_t)NMAX * HDIM];   // 51.2 MB
__device__ int2  g_pairs[(size_t)KEEPK * NMAX];              // 100.8 MB
__device__ int   g_cnt[KEEPK];
__device__ int   g_tiles[MAXTILES];
__device__ int   g_ntiles;

typedef unsigned long long u64;

__device__ __forceinline__ void ffma2(u64 &acc, u64 a, u64 b) {
    asm("fma.rn.f32x2 %0, %1, %2, %0;" : "+l"(acc) : "l"(a), "l"(b));
}
__device__ __forceinline__ float pairsum(u64 v) {
    return __uint_as_float((unsigned)v) + __uint_as_float((unsigned)(v >> 32));
}
__device__ __forceinline__ float eluf(float v) {
    return v > 0.f ? v : expm1f(v);
}
__device__ __forceinline__ void red_add_v4(float* p, float a, float b, float c, float d) {
    asm volatile("red.global.add.v4.f32 [%0], {%1, %2, %3, %4};"
                 :: "l"(p), "f"(a), "f"(b), "f"(c), "f"(d) : "memory");
}

// ---------------------------------------------------------------------------
// kZ: zero accumulator + per-offset counters
// ---------------------------------------------------------------------------
__global__ void kz_kernel(int nvec)
{
    float4 z = make_float4(0.f, 0.f, 0.f, 0.f);
    for (int i = blockIdx.x * blockDim.x + threadIdx.x; i < nvec;
         i += gridDim.x * blockDim.x)
        ((float4*)g_acc)[i] = z;
    if (blockIdx.x == 0 && threadIdx.x < KEEPK) g_cnt[threadIdx.x] = 0;
}

// ---------------------------------------------------------------------------
// k1: f = elu( elu(x+y) @ Wa )   [N,128]@[128,64] -> [N,64]
// ---------------------------------------------------------------------------
#define SA_STRIDE 132

__global__ __launch_bounds__(256, 2)
void k1_kernel(const float* __restrict__ x, const float* __restrict__ y,
               const float* __restrict__ Wa, int N)
{
    extern __shared__ float sm[];
    float* sWa = sm;            // 8192 (pair-major Wa)
    float* sA  = sm + 8192;     // 64*132 = 8448

    int tid = threadIdx.x;
    int r0  = blockIdx.x * 64;

    for (int j = tid; j < 2048; j += 256) {
        int d = j >> 4, c0 = (j & 15) * 4;
        float4 w = *(const float4*)&Wa[d * 64 + c0];
        int base = (d >> 1) * 128 + (d & 1);
        sWa[base + 2 * (c0 + 0)] = w.x;
        sWa[base + 2 * (c0 + 1)] = w.y;
        sWa[base + 2 * (c0 + 2)] = w.z;
        sWa[base + 2 * (c0 + 3)] = w.w;
    }
    for (int j = tid; j < 2048; j += 256) {
        int r = j >> 5, c0 = (j & 31) * 4;
        int gr = r0 + r;
        float4 v = make_float4(0.f, 0.f, 0.f, 0.f);
        if (gr < N) {
            float4 xv = *(const float4*)&x[(size_t)gr * CDIM + c0];
            float4 yv = *(const float4*)&y[(size_t)gr * CDIM + c0];
            v.x = eluf(xv.x + yv.x); v.y = eluf(xv.y + yv.y);
            v.z = eluf(xv.z + yv.z); v.w = eluf(xv.w + yv.w);
        }
        *(float4*)&sA[r * SA_STRIDE + c0] = v;
    }
    __syncthreads();

    int wid = tid >> 5, lane = tid & 31;
    int cg = lane & 15, rg = lane >> 4;
    int rbase = wid * 8 + rg * 4;

    u64 acc[4][4];
    #pragma unroll
    for (int i = 0; i < 4; i++)
        #pragma unroll
        for (int j = 0; j < 4; j++) acc[i][j] = 0ull;

    #pragma unroll 4
    for (int dp = 0; dp < 64; dp++) {
        u64 a_[4];
        #pragma unroll
        for (int i = 0; i < 4; i++)
            a_[i] = *(const u64*)&sA[(rbase + i) * SA_STRIDE + 2 * dp];
        ulonglong2 w0 = *(const ulonglong2*)&sWa[dp * 128 + 8 * cg];
        ulonglong2 w1 = *(const ulonglong2*)&sWa[dp * 128 + 8 * cg + 4];
        #pragma unroll
        for (int i = 0; i < 4; i++) {
            ffma2(acc[i][0], a_[i], w0.x);
            ffma2(acc[i][1], a_[i], w0.y);
            ffma2(acc[i][2], a_[i], w1.x);
            ffma2(acc[i][3], a_[i], w1.y);
        }
    }
    // lane owns out channels 4cg..4cg+3 (contiguous)
    #pragma unroll
    for (int i = 0; i < 4; i++) {
        int grow = r0 + rbase + i;
        if (grow < N) {
            float4 v;
            v.x = eluf(pairsum(acc[i][0]));
            v.y = eluf(pairsum(acc[i][1]));
            v.z = eluf(pairsum(acc[i][2]));
            v.w = eluf(pairsum(acc[i][3]));
            *(float4*)&g_f[(size_t)grow * HDIM + 4 * cg] = v;
        }
    }
}

// ---------------------------------------------------------------------------
// kA: global compaction. grid = (ceil(N/256), 63). Warp-aggregated atomics.
// ---------------------------------------------------------------------------
__global__ void ka_kernel(const int* __restrict__ nidx, int N)
{
    int k = blockIdx.y;
    int r = blockIdx.x * blockDim.x + threadIdx.x;
    int idx = -1;
    if (r < N) idx = nidx[(size_t)k * N + r];
    bool valid = idx >= 0;
    unsigned m = __ballot_sync(0xffffffffu, valid);
    int lane = threadIdx.x & 31;
    int base = 0;
    if (lane == 0 && m) base = atomicAdd(&g_cnt[k], __popc(m));
    base = __shfl_sync(0xffffffffu, base, 0);
    if (valid) {
        int pos = base + __popc(m & ((1u << lane) - 1));
        g_pairs[(size_t)k * NMAX + pos] = make_int2(r, idx);
    }
}

// ---------------------------------------------------------------------------
// kT: build flat tile list. grid = 63 blocks (one per offset).
// ---------------------------------------------------------------------------
__global__ void kt_kernel()
{
    int k = blockIdx.x;
    __shared__ int s_base;
    if (threadIdx.x == 0) {
        int s = 0;
        #pragma unroll 9
        for (int i = 0; i < KEEPK; i++) {
            int nt = (g_cnt[i] + 63) >> 6;
            if (i < k) s += nt;
            if (k == KEEPK - 1 && i == KEEPK - 1) g_ntiles = s + nt;
        }
        s_base = s;
    }
    __syncthreads();
    int nt = (g_cnt[k] + 63) >> 6;
    int b = s_base;
    for (int t = threadIdx.x; t < nt; t += blockDim.x)
        g_tiles[b + t] = (k << 16) | t;
}

// ---------------------------------------------------------------------------
// kB: persistent blocks, contiguous tile chunks, double-buffered gather,
// 8 warps x 8 rows GEMM, red.global.add.v4 scatter.
// ---------------------------------------------------------------------------
#define FB_STRIDE 68   // 272 B/row: 16B-aligned rows

__global__ __launch_bounds__(256, 2)
void kb_kernel(const float* __restrict__ Wb)
{
    extern __shared__ float sm[];
    float* sWb = sm;                      // 4096 (pair-major Wb[k])
    float* fbs0 = sm + 4096;              // 64*68 = 4352
    float* fbs1 = sm + 8448;              // 4352
    int* sos0 = (int*)(sm + 12800);       // 64
    int* sos1 = sos0 + 64;                // 64

    int tid = threadIdx.x;
    int wid = tid >> 5, lane = tid & 31;
    int cg = lane & 15, rg = lane >> 4;
    int vb = wid * 8 + rg * 4;

    int grow_ = tid >> 2;        // row in tile handled for gather (0..63)
    int gq    = (tid & 3) * 16;  // column start (floats)

    int ntiles = g_ntiles;
    int chunk = (ntiles + gridDim.x - 1) / gridDim.x;
    int t0 = blockIdx.x * chunk;
    int t1 = min(t0 + chunk, ntiles);
    if (t0 >= t1) return;

    int kprev = -1;

    // prolog: gather tile t0 into buffer 0
    {
        int d = g_tiles[t0];
        int k = d >> 16, t = d & 0xffff;
        int cc = min(64, g_cnt[k] - t * 64);
        int2 pr = make_int2(-1, 0);
        if (grow_ < cc) pr = g_pairs[(size_t)k * NMAX + t * 64 + grow_];
        float4 gv[4];
        #pragma unroll
        for (int q = 0; q < 4; q++) gv[q] = make_float4(0.f, 0.f, 0.f, 0.f);
        if (pr.x >= 0) {
            const float* src = &g_f[(size_t)pr.y * HDIM + gq];
            #pragma unroll
            for (int q = 0; q < 4; q++) gv[q] = *(const float4*)(src + 4 * q);
        }
        #pragma unroll
        for (int q = 0; q < 4; q++)
            *(float4*)&fbs0[grow_ * FB_STRIDE + gq + 4 * q] = gv[q];
        if ((tid & 3) == 0) sos0[grow_] = pr.x;
    }

    for (int tl = t0; tl < t1; tl++) {
        int cur = (tl - t0) & 1;
        int k = g_tiles[tl] >> 16;

        if (k != kprev) {
            __syncthreads();   // protect sWb from previous GEMM readers
            for (int j = tid; j < 1024; j += 256) {
                int dd = j >> 4, c0 = (j & 15) * 4;
                float4 w = *(const float4*)&Wb[(size_t)k * 4096 + dd * 64 + c0];
                int base = (dd >> 1) * 128 + (dd & 1);
                sWb[base + 2 * (c0 + 0)] = w.x;
                sWb[base + 2 * (c0 + 1)] = w.y;
                sWb[base + 2 * (c0 + 2)] = w.z;
                sWb[base + 2 * (c0 + 3)] = w.w;
            }
            kprev = k;
        }
        __syncthreads();   // fbuf[cur] + sWb ready

        // prefetch next tile into registers (lands during GEMM)
        float4 gv[4];
        int orow_next = -1;
        bool has_next = (tl + 1 < t1);
        if (has_next) {
            int dn = g_tiles[tl + 1];
            int kn = dn >> 16, tn = dn & 0xffff;
            int ccn = min(64, g_cnt[kn] - tn * 64);
            int2 pr = make_int2(-1, 0);
            if (grow_ < ccn) pr = g_pairs[(size_t)kn * NMAX + tn * 64 + grow_];
            orow_next = pr.x;
            #pragma unroll
            for (int q = 0; q < 4; q++) gv[q] = make_float4(0.f, 0.f, 0.f, 0.f);
            if (pr.x >= 0) {
                const float* src = &g_f[(size_t)pr.y * HDIM + gq];
                #pragma unroll
                for (int q = 0; q < 4; q++) gv[q] = *(const float4*)(src + 4 * q);
            }
        }

        // GEMM on fbuf[cur]
        const float* fbuf = cur ? fbs1 : fbs0;
        const int*   so   = cur ? sos1 : sos0;

        u64 acc[4][4];
        #pragma unroll
        for (int i = 0; i < 4; i++)
            #pragma unroll
            for (int j = 0; j < 4; j++) acc[i][j] = 0ull;

        #pragma unroll 4
        for (int dp = 0; dp < 32; dp++) {
            u64 a_[4];
            #pragma unroll
            for (int i = 0; i < 4; i++)
                a_[i] = *(const u64*)&fbuf[(vb + i) * FB_STRIDE + 2 * dp];
            ulonglong2 w0 = *(const ulonglong2*)&sWb[dp * 128 + 8 * cg];
            ulonglong2 w1 = *(const ulonglong2*)&sWb[dp * 128 + 8 * cg + 4];
            #pragma unroll
            for (int i = 0; i < 4; i++) {
                ffma2(acc[i][0], a_[i], w0.x);
                ffma2(acc[i][1], a_[i], w0.y);
                ffma2(acc[i][2], a_[i], w1.x);
                ffma2(acc[i][3], a_[i], w1.y);
            }
        }
        #pragma unroll
        for (int i = 0; i < 4; i++) {
            int orow = so[vb + i];
            if (orow >= 0) {
                red_add_v4(&g_acc[(size_t)orow * HDIM + 4 * cg],
                           pairsum(acc[i][0]), pairsum(acc[i][1]),
                           pairsum(acc[i][2]), pairsum(acc[i][3]));
            }
        }

        // commit prefetched tile to the other buffer
        if (has_next) {
            float* fbn = cur ? fbs0 : fbs1;
            int*   son = cur ? sos0 : sos1;
            #pragma unroll
            for (int q = 0; q < 4; q++)
                *(float4*)&fbn[grow_ * FB_STRIDE + gq + 4 * q] = gv[q];
            if ((tid & 3) == 0) son[grow_] = orow_next;
        }
    }
}

// ---------------------------------------------------------------------------
// k3: out = x + elu(g_acc) @ Wc     [N,64]@[64,128]
// ---------------------------------------------------------------------------
#define HS_STRIDE 68

__global__ __launch_bounds__(256, 2)
void k3_kernel(const float* __restrict__ Wc, const float* __restrict__ x,
               float* __restrict__ out, int N)
{
    extern __shared__ float sm[];
    float* sWc = sm;              // 8192 (pair-major Wc)
    float* hS  = sm + 8192;       // 64*68 = 4352

    int tid = threadIdx.x;
    int wid = tid >> 5, lane = tid & 31;
    int r0 = blockIdx.x * 64;

    for (int j = tid; j < 2048; j += 256) {
        int d = j >> 5, c0 = (j & 31) * 4;
        float4 w = *(const float4*)&Wc[d * 128 + c0];
        int base = (d >> 1) * 256 + (d & 1);
        sWc[base + 2 * (c0 + 0)] = w.x;
        sWc[base + 2 * (c0 + 1)] = w.y;
        sWc[base + 2 * (c0 + 2)] = w.z;
        sWc[base + 2 * (c0 + 3)] = w.w;
    }
    for (int j = tid; j < 1024; j += 256) {
        int r = j >> 4, q = (j & 15) * 4;
        int gr = r0 + r;
        float4 v = make_float4(0.f, 0.f, 0.f, 0.f);
        if (gr < N) {
            v = *(const float4*)&g_acc[(size_t)gr * HDIM + q];
            v.x = eluf(v.x); v.y = eluf(v.y);
            v.z = eluf(v.z); v.w = eluf(v.w);
        }
        *(float4*)&hS[r * HS_STRIDE + q] = v;
    }
    __syncthreads();

    // lane owns channels {2l, 2l+1, 2l+64, 2l+65}
    #pragma unroll
    for (int h = 0; h < 2; h++) {
        int rbase = wid * 8 + h * 4;
        u64 acc[4][4];
        #pragma unroll
        for (int i = 0; i < 4; i++)
            #pragma unroll
            for (int j = 0; j < 4; j++) acc[i][j] = 0ull;

        #pragma unroll 4
        for (int dp = 0; dp < 32; dp++) {
            u64 a_[4];
            #pragma unroll
            for (int i = 0; i < 4; i++)
                a_[i] = *(const u64*)&hS[(rbase + i) * HS_STRIDE + 2 * dp];
            ulonglong2 w0 = *(const ulonglong2*)&sWc[dp * 256 + 4 * lane];
            ulonglong2 w1 = *(const ulonglong2*)&sWc[dp * 256 + 128 + 4 * lane];
            #pragma unroll
            for (int i = 0; i < 4; i++) {
                ffma2(acc[i][0], a_[i], w0.x);
                ffma2(acc[i][1], a_[i], w0.y);
                ffma2(acc[i][2], a_[i], w1.x);
                ffma2(acc[i][3], a_[i], w1.y);
            }
        }
        #pragma unroll
        for (int i = 0; i < 4; i++) {
            int grow = r0 + rbase + i;
            if (grow < N) {
                float2 xv0 = *(const float2*)&x[(size_t)grow * CDIM + 2 * lane];
                float2 xv1 = *(const float2*)&x[(size_t)grow * CDIM + 2 * lane + 64];
                float2 o0, o1;
                o0.x = xv0.x + pairsum(acc[i][0]);
                o0.y = xv0.y + pairsum(acc[i][1]);
                o1.x = xv1.x + pairsum(acc[i][2]);
                o1.y = xv1.y + pairsum(acc[i][3]);
                *(float2*)&out[(size_t)grow * CDIM + 2 * lane]      = o0;
                *(float2*)&out[(size_t)grow * CDIM + 2 * lane + 64] = o1;
            }
        }
    }
}

// ---------------------------------------------------------------------------
extern "C" void kernel_launch(void* const* d_in, const int* in_sizes, int n_in,
                              void* d_out, int out_size)
{
    const float* x    = (const float*)d_in[0];
    const float* y    = (const float*)d_in[1];
    const float* Wa   = (const float*)d_in[2];
    const float* Wb   = (const float*)d_in[3];
    const float* Wc   = (const float*)d_in[4];
    const int*   nidx = (const int*)  d_in[5];
    float* out = (float*)d_out;

    int N = in_sizes[0] / CDIM;

    const int SMEM1 = (8192 + 64 * SA_STRIDE) * (int)sizeof(float);        // 66560
    const int SMEMB = 12800 * (int)sizeof(float) + 128 * (int)sizeof(int); // 51712
    const int SMEM3 = (8192 + 64 * HS_STRIDE) * (int)sizeof(float);        // 50176

    cudaFuncSetAttribute(k1_kernel, cudaFuncAttributeMaxDynamicSharedMemorySize, SMEM1);
    cudaFuncSetAttribute(kb_kernel, cudaFuncAttributeMaxDynamicSharedMemorySize, SMEMB);
    cudaFuncSetAttribute(k3_kernel, cudaFuncAttributeMaxDynamicSharedMemorySize, SMEM3);

    int gridRows = (N + 63) / 64;

    kz_kernel<<<592, 256>>>(N * (HDIM / 4));
    k1_kernel<<<gridRows, 256, SMEM1>>>(x, y, Wa, N);
    ka_kernel<<<dim3((N + 255) / 256, KEEPK), 256>>>(nidx, N);
    kt_kernel<<<KEEPK, 256>>>();
    kb_kernel<<<296, 256, SMEMB>>>(Wb);
    k3_kernel<<<gridRows, 256, SMEM3>>>(Wc, x, out, N);
}